// round 4
// baseline (speedup 1.0000x reference)
#include <cuda_runtime.h>

// Fused: ConvTranspose3d(3->16, k=3, s=2, p=1, out_pad=1) + bias + MaxPool3d(2)
//        + softmax(ch) - subtract, swish, max(ch).
// Input  x: [4,3,64,64,64] f32, w: [3,16,3,3,3], b: [16], subtract: [16]
// Output: [4,64,64,64] f32
//
// Final voxel (n,d,h,w) depends only on x[n, :, d..d+1, h..h+1, w..w+1].
// Lane c=lane&15 owns channel c; half=lane>>4 picks one of 2 adjacent-w voxels.
// R4: ILP-4 batching (R2) + softmax WITHOUT the max-subtraction pass —
// conv outputs are bounded (|m| << 88), exp(m) is finite, softmax is
// shift-invariant. Removes one of three shuffle-reduction chains and the
// serial dependency in front of exp.

#define N_BATCH 4
#define CIN 3
#define COUT 16
#define DIM 64
#define TILE_W 66
#define JB 4   // voxel-pairs per batch

__global__ __launch_bounds__(128) void fused_ctmp_softswish_kernel(
    const float* __restrict__ x,
    const float* __restrict__ wgt,
    const float* __restrict__ bias_g,
    const float* __restrict__ sub_g,
    float* __restrict__ out)
{
    __shared__ float tile[4][12][TILE_W];

    const int lane = threadIdx.x & 31;
    const int wid  = threadIdx.x >> 5;
    const int c    = lane & 15;
    const int half = lane >> 4;

    // weights for channel c (81 floats) in registers
    float wr[81];
    #pragma unroll
    for (int cin = 0; cin < CIN; ++cin) {
        #pragma unroll
        for (int k = 0; k < 27; ++k)
            wr[cin * 27 + k] = __ldg(&wgt[(cin * COUT + c) * 27 + k]);
    }
    const float bias = __ldg(&bias_g[c]);
    const float subc = __ldg(&sub_g[c]);

    // parity tap tables: even conv pos -> k=1 @ off 0; odd -> k=2 @ off 0, k=0 @ off 1
    const int NP[2]      = {1, 2};
    const int KTAP[2][2] = {{1, 0}, {2, 0}};
    const int XOFF[2][2] = {{0, 0}, {0, 1}};

    const int gwarp  = blockIdx.x * 4 + wid;
    const int nwarps = gridDim.x * 4;
    const int nrows  = N_BATCH * DIM * DIM;

    for (int row = gwarp; row < nrows; row += nwarps) {
        const int h = row & 63;
        const int d = (row >> 6) & 63;
        const int n = row >> 12;

        // cooperative per-warp tile load: [cin*4 + dd*2 + hh][wpos]
        #pragma unroll
        for (int comb = 0; comb < 12; ++comb) {
            const int cin = comb >> 2;
            const int dd  = (comb >> 1) & 1;
            const int hh  = comb & 1;
            const int dcur = d + dd;
            const int hcur = h + hh;
            const bool rowok = (dcur < DIM) && (hcur < DIM);
            const float* src = x + (((n * CIN + cin) * DIM + dcur) * DIM + hcur) * DIM;
            for (int wp = lane; wp < TILE_W; wp += 32) {
                float v = 0.f;
                if (rowok && wp < DIM) v = __ldg(&src[wp]);
                tile[wid][comb][wp] = v;
            }
        }
        __syncwarp();

        const float* tw = &tile[wid][0][0];
        float* orow = out + ((n * DIM + d) * DIM + h) * DIM;

        for (int w0 = 0; w0 < DIM; w0 += 2 * JB) {
            float m[JB];

            // ---- compute phase: 4 independent voxel-pairs ----
            #pragma unroll
            for (int j = 0; j < JB; ++j) {
                const int wv = w0 + 2 * j + half;

                float acc[8];
                #pragma unroll
                for (int i = 0; i < 8; ++i) acc[i] = 0.f;

                #pragma unroll
                for (int cin = 0; cin < CIN; ++cin) {
                    #pragma unroll
                    for (int dd = 0; dd < 2; ++dd) {
                        #pragma unroll
                        for (int hh = 0; hh < 2; ++hh) {
                            const int comb = cin * 4 + dd * 2 + hh;
                            const float x0 = tw[comb * TILE_W + wv];
                            const float x1 = tw[comb * TILE_W + wv + 1];
                            const float xx[2] = {x0, x1};
                            #pragma unroll
                            for (int pd = 0; pd < 2; ++pd) {
                                #pragma unroll
                                for (int jd = 0; jd < 2; ++jd) {
                                    if (jd >= NP[pd] || XOFF[pd][jd] != dd) continue;
                                    const int kd = KTAP[pd][jd];
                                    #pragma unroll
                                    for (int ph = 0; ph < 2; ++ph) {
                                        #pragma unroll
                                        for (int jh = 0; jh < 2; ++jh) {
                                            if (jh >= NP[ph] || XOFF[ph][jh] != hh) continue;
                                            const int kh = KTAP[ph][jh];
                                            #pragma unroll
                                            for (int pw = 0; pw < 2; ++pw) {
                                                #pragma unroll
                                                for (int jw = 0; jw < 2; ++jw) {
                                                    if (jw >= NP[pw]) continue;
                                                    const int kw = KTAP[pw][jw];
                                                    const float wv_ = wr[cin * 27 + kd * 9 + kh * 3 + kw];
                                                    acc[pd * 4 + ph * 2 + pw] =
                                                        fmaf(wv_, xx[XOFF[pw][jw]], acc[pd * 4 + ph * 2 + pw]);
                                                }
                                            }
                                        }
                                    }
                                }
                            }
                        }
                    }
                }

                float mm = fmaxf(fmaxf(fmaxf(acc[0], acc[1]), fmaxf(acc[2], acc[3])),
                                 fmaxf(fmaxf(acc[4], acc[5]), fmaxf(acc[6], acc[7])));
                m[j] = mm + bias;
            }

            // ---- reduction phase: no max-pass; 2 chains interleaved (ILP=4) ----
            float e[JB], sum[JB];
            #pragma unroll
            for (int j = 0; j < JB; ++j) {
                e[j] = __expf(m[j]);
                sum[j] = e[j];
            }
            #pragma unroll
            for (int s = 1; s < 16; s <<= 1) {
                #pragma unroll
                for (int j = 0; j < JB; ++j)
                    sum[j] += __shfl_xor_sync(0xffffffffu, sum[j], s);
            }

            float r[JB];
            #pragma unroll
            for (int j = 0; j < JB; ++j) {
                const float sft = __fdividef(e[j], sum[j]);
                const float z   = sft - subc;
                r[j] = __fdividef(z, 1.f + __expf(-z));   // swish
            }
            #pragma unroll
            for (int s = 1; s < 16; s <<= 1) {
                #pragma unroll
                for (int j = 0; j < JB; ++j)
                    r[j] = fmaxf(r[j], __shfl_xor_sync(0xffffffffu, r[j], s));
            }

            if (c == 0) {
                #pragma unroll
                for (int j = 0; j < JB; ++j)
                    orow[w0 + 2 * j + half] = r[j];
            }
        }
        __syncwarp();
    }
}

extern "C" void kernel_launch(void* const* d_in, const int* in_sizes, int n_in,
                              void* d_out, int out_size) {
    const float* x   = (const float*)d_in[0];
    const float* w   = (const float*)d_in[1];
    const float* b   = (const float*)d_in[2];
    const float* sub = (const float*)d_in[3];
    float* out = (float*)d_out;
    (void)in_sizes; (void)n_in; (void)out_size;
    fused_ctmp_softswish_kernel<<<2048, 128>>>(x, w, b, sub, out);
}

// round 5
// speedup vs baseline: 1.4825x; 1.4825x over previous
#include <cuda_runtime.h>

// Fused: ConvTranspose3d(3->16, k=3, s=2, p=1, out_pad=1) + bias + MaxPool3d(2)
//        + softmax(ch) - subtract, swish, max(ch).
// x: [4,3,64,64,64] f32, w: [3,16,3,3,3], b: [16], subtract: [16] -> out [4,64,64,64]
//
// Lane c=lane&15 owns channel c; half=lane>>4 owns one of 2 adjacent-w voxels.
// R5: parity-split float4 smem tile -> one broadcast LDS.128 feeds one comb for
// TWO voxel-pairs (24 LDS/batch vs 96). Softmax without max-pass (bounded m).

#define N_BATCH 4
#define CIN 3
#define COUT 16
#define DIM 64

__global__ __launch_bounds__(128, 4) void fused_ctmp_softswish_kernel(
    const float* __restrict__ x,
    const float* __restrict__ wgt,
    const float* __restrict__ bias_g,
    const float* __restrict__ sub_g,
    float* __restrict__ out)
{
    // tile[warp][comb][p][q] = {x_row[4q+p], x[4q+p+1], x[4q+p+2], x[4q+p+3]}
    // comb = cin*4 + dd*2 + hh ; p = w-parity (half) ; q = 0..15
    __shared__ float4 tile[4][12][2][16];

    const int lane = threadIdx.x & 31;
    const int wid  = threadIdx.x >> 5;
    const int c    = lane & 15;
    const int half = lane >> 4;

    // weights for channel c (81 floats) in registers
    float wr[81];
    #pragma unroll
    for (int cin = 0; cin < CIN; ++cin) {
        #pragma unroll
        for (int k = 0; k < 27; ++k)
            wr[cin * 27 + k] = __ldg(&wgt[(cin * COUT + c) * 27 + k]);
    }
    const float bias = __ldg(&bias_g[c]);
    const float subc = __ldg(&sub_g[c]);

    // parity tap tables: even conv pos -> k=1 @ off 0; odd -> k=2 @ off 0, k=0 @ off 1
    const int NP[2]      = {1, 2};
    const int KTAP[2][2] = {{1, 0}, {2, 0}};
    const int XOFF[2][2] = {{0, 0}, {0, 1}};

    const int gwarp  = blockIdx.x * 4 + wid;
    const int nwarps = gridDim.x * 4;
    const int nrows  = N_BATCH * DIM * DIM;

    // per-lane build coords: each iteration covers one comb; lane -> (p,q)
    const int bp = lane >> 4;
    const int bq = lane & 15;

    for (int row = gwarp; row < nrows; row += nwarps) {
        const int h = row & 63;
        const int d = (row >> 6) & 63;
        const int n = row >> 12;

        // ---- build parity-split float4 tile (12 iterations, 1 comb each) ----
        #pragma unroll
        for (int comb = 0; comb < 12; ++comb) {
            const int cin = comb >> 2;
            const int dd  = (comb >> 1) & 1;
            const int hh  = comb & 1;
            const int dcur = d + dd;
            const int hcur = h + hh;
            const bool rowok = (dcur < DIM) && (hcur < DIM);
            const float* src = x + (((n * CIN + cin) * DIM + dcur) * DIM + hcur) * DIM;
            const int base = 4 * bq + bp;
            float a0 = 0.f, a1 = 0.f, a2 = 0.f, a3 = 0.f;
            if (rowok) {
                a0 = __ldg(&src[base]);          // base <= 61 always < 64
                a1 = __ldg(&src[base + 1]);      // <= 62
                a2 = __ldg(&src[base + 2]);      // <= 63
                if (base + 3 < DIM) a3 = __ldg(&src[base + 3]);
            }
            tile[wid][comb][bp][bq] = make_float4(a0, a1, a2, a3);
        }
        __syncwarp();

        float* orow = out + ((n * DIM + d) * DIM + h) * DIM;

        for (int w0 = 0; w0 < DIM; w0 += 8) {
            const int q0 = w0 >> 2;
            float m[4];

            // ---- compute: 2 jp-groups x 2 voxel-pairs, comb-outer ----
            #pragma unroll
            for (int jp = 0; jp < 2; ++jp) {
                float acc[2][8];
                #pragma unroll
                for (int jj = 0; jj < 2; ++jj)
                    #pragma unroll
                    for (int i = 0; i < 8; ++i) acc[jj][i] = 0.f;

                #pragma unroll
                for (int comb = 0; comb < 12; ++comb) {
                    const int cin = comb >> 2;
                    const int dd  = (comb >> 1) & 1;
                    const int hh  = comb & 1;
                    const float4 v = tile[wid][comb][half][q0 + jp];
                    const float xxs[2][2] = {{v.x, v.y}, {v.z, v.w}};

                    #pragma unroll
                    for (int pd = 0; pd < 2; ++pd) {
                        #pragma unroll
                        for (int jd = 0; jd < 2; ++jd) {
                            if (jd >= NP[pd] || XOFF[pd][jd] != dd) continue;
                            const int kd = KTAP[pd][jd];
                            #pragma unroll
                            for (int ph = 0; ph < 2; ++ph) {
                                #pragma unroll
                                for (int jh = 0; jh < 2; ++jh) {
                                    if (jh >= NP[ph] || XOFF[ph][jh] != hh) continue;
                                    const int kh = KTAP[ph][jh];
                                    #pragma unroll
                                    for (int pw = 0; pw < 2; ++pw) {
                                        #pragma unroll
                                        for (int jw = 0; jw < 2; ++jw) {
                                            if (jw >= NP[pw]) continue;
                                            const int kw = KTAP[pw][jw];
                                            const float wv_ = wr[cin * 27 + kd * 9 + kh * 3 + kw];
                                            const int ww = XOFF[pw][jw];
                                            #pragma unroll
                                            for (int jj = 0; jj < 2; ++jj)
                                                acc[jj][pd * 4 + ph * 2 + pw] =
                                                    fmaf(wv_, xxs[jj][ww], acc[jj][pd * 4 + ph * 2 + pw]);
                                        }
                                    }
                                }
                            }
                        }
                    }
                }

                #pragma unroll
                for (int jj = 0; jj < 2; ++jj) {
                    const float* a = acc[jj];
                    float mm = fmaxf(fmaxf(fmaxf(a[0], a[1]), fmaxf(a[2], a[3])),
                                     fmaxf(fmaxf(a[4], a[5]), fmaxf(a[6], a[7])));
                    m[2 * jp + jj] = mm + bias;
                }
            }

            // ---- epilogue: no softmax max-pass; 2 chains interleaved (ILP=4) ----
            float e[4], sum[4];
            #pragma unroll
            for (int j = 0; j < 4; ++j) {
                e[j] = __expf(m[j]);
                sum[j] = e[j];
            }
            #pragma unroll
            for (int s = 1; s < 16; s <<= 1) {
                #pragma unroll
                for (int j = 0; j < 4; ++j)
                    sum[j] += __shfl_xor_sync(0xffffffffu, sum[j], s);
            }

            float r[4];
            #pragma unroll
            for (int j = 0; j < 4; ++j) {
                const float sft = __fdividef(e[j], sum[j]);
                const float z   = sft - subc;
                r[j] = __fdividef(z, 1.f + __expf(-z));   // swish
            }
            #pragma unroll
            for (int s = 1; s < 16; s <<= 1) {
                #pragma unroll
                for (int j = 0; j < 4; ++j)
                    r[j] = fmaxf(r[j], __shfl_xor_sync(0xffffffffu, r[j], s));
            }

            if (c == 0) {
                #pragma unroll
                for (int j = 0; j < 4; ++j)
                    orow[w0 + 2 * j + half] = r[j];
            }
        }
        __syncwarp();
    }
}

extern "C" void kernel_launch(void* const* d_in, const int* in_sizes, int n_in,
                              void* d_out, int out_size) {
    const float* x   = (const float*)d_in[0];
    const float* w   = (const float*)d_in[1];
    const float* b   = (const float*)d_in[2];
    const float* sub = (const float*)d_in[3];
    float* out = (float*)d_out;
    (void)in_sizes; (void)n_in; (void)out_size;
    fused_ctmp_softswish_kernel<<<2048, 128>>>(x, w, b, sub, out);
}